// round 4
// baseline (speedup 1.0000x reference)
#include <cuda_runtime.h>

#define NTH  256          // threads per block
#define SLOPE 0.0025f
typedef unsigned long long u64;

struct Params { const float* p[27]; };

// ---------- packed f32x2 primitives (Blackwell sm_103a) ----------
__device__ __forceinline__ u64 ffma2(u64 a, u64 b, u64 c) {
    u64 d; asm("fma.rn.f32x2 %0,%1,%2,%3;" : "=l"(d) : "l"(a), "l"(b), "l"(c)); return d;
}
__device__ __forceinline__ u64 fmul2(u64 a, u64 b) {
    u64 d; asm("mul.rn.f32x2 %0,%1,%2;" : "=l"(d) : "l"(a), "l"(b)); return d;
}
__device__ __forceinline__ u64 fadd2(u64 a, u64 b) {
    u64 d; asm("add.rn.f32x2 %0,%1,%2;" : "=l"(d) : "l"(a), "l"(b)); return d;
}
__device__ __forceinline__ u64 pack2(float lo, float hi) {
    u64 d; asm("mov.b64 %0,{%1,%2};" : "=l"(d) : "f"(lo), "f"(hi)); return d;
}
__device__ __forceinline__ void unpack2(u64 v, float& lo, float& hi) {
    asm("mov.b64 {%0,%1},%2;" : "=f"(lo), "=f"(hi) : "l"(v));
}
__device__ __forceinline__ u64 abs2(u64 v) {
    u64 d; asm("and.b64 %0,%1,0x7FFFFFFF7FFFFFFF;" : "=l"(d) : "l"(v)); return d;
}
// Branchless packed leaky-relu: rr(v) = c1*v + c2*|v|, c1=(1+s)/2, c2=(1-s)/2.
// v>=0: (c1+c2)v = v ; v<0: (c1-c2)v = s*v.  Exact in the algebra; <=1ulp rounding.
__device__ __forceinline__ u64 rr2(u64 v) {
    const u64 C1 = pack2(0.50125f, 0.50125f);
    const u64 C2 = pack2(0.49875f, 0.49875f);
    return ffma2(v, C1, fmul2(abs2(v), C2));
}

// ---------- shared-memory weight offsets (u64 slots, weights duplicated) ----------
// W_in(64) b_in(8) W_h1(32) b_h1(4) W_h2(16) b_h2(4) W_h3(16) b_h3(4)
// W_h4(16) b_h4(4) W_h5(16) b_h5(4) W_enc(4) b_enc(1) W_h6(4) b_h6(4)
// W_h7(16) b_h7(4) W_h8(16) b_h8(4) W_h9(16) b_h9(4) W_h10(16) b_h10(4)
// W_dec(32) b_dec(8)  => total 321 u64
#define O_W_IN   0
#define O_B_IN   64
#define O_W_H1   72
#define O_B_H1   104
#define O_W_H2   108
#define O_B_H2   124
#define O_W_H3   128
#define O_B_H3   144
#define O_W_H4   148
#define O_B_H4   164
#define O_W_H5   168
#define O_B_H5   184
#define O_W_EN   188
#define O_B_EN   192
#define O_W_H6   193
#define O_B_H6   197
#define O_W_H7   201
#define O_B_H7   217
#define O_W_H8   221
#define O_B_H8   237
#define O_W_H9   241
#define O_B_H9   257
#define O_W_HA   261
#define O_B_HA   277
#define O_W_DE   281
#define O_B_DE   313
#define S_TOTAL  321

// dst[p][j] = (ACT ? rr2 : id)( {b,b} + sum_i src[p][i] * {w,w} )   for 2 row-pairs
template<int FI, int FO, bool ACT>
__device__ __forceinline__ void lin(const u64* __restrict__ s, int Woff, int boff,
                                    const u64 (&src)[2][8], u64 (&dst)[2][8]) {
#pragma unroll
    for (int j = 0; j < FO; j++) {
        u64 b = s[boff + j];
        u64 a0 = b, a1 = b;
#pragma unroll
        for (int i = 0; i < FI; i++) {
            u64 w = s[Woff + i * FO + j];          // one LDS.64 feeds both pairs
            a0 = ffma2(src[0][i], w, a0);
            a1 = ffma2(src[1][i], w, a1);
        }
        dst[0][j] = ACT ? rr2(a0) : a0;
        dst[1][j] = ACT ? rr2(a1) : a1;
    }
}

// dst[p][j] += {b,b} + sum_i src[p][i] * {w,w}    (residual, no activation)
template<int FI, int FO>
__device__ __forceinline__ void lin_add(const u64* __restrict__ s, int Woff, int boff,
                                        const u64 (&src)[2][8], u64 (&dst)[2][8]) {
#pragma unroll
    for (int j = 0; j < FO; j++) {
        u64 b = s[boff + j];
        u64 a0 = b, a1 = b;
#pragma unroll
        for (int i = 0; i < FI; i++) {
            u64 w = s[Woff + i * FO + j];
            a0 = ffma2(src[0][i], w, a0);
            a1 = ffma2(src[1][i], w, a1);
        }
        dst[0][j] = fadd2(dst[0][j], a0);
        dst[1][j] = fadd2(dst[1][j], a1);
    }
}

__global__ __launch_bounds__(NTH)
void ann_fused_kernel(Params P, float* __restrict__ out, int N) {
    __shared__ u64 s[S_TOTAL];

    // Cooperative weight load: duplicate each scalar weight into both f32x2 lanes.
    {
        const int sz[26] = {64,8,32,4,16,4,16,4,16,4,16,4,4,1,4,4,16,4,16,4,16,4,16,4,32,8};
        int off = 0;
        for (int k = 0; k < 26; k++) {
            const float* src = P.p[k + 1];
            for (int i = threadIdx.x; i < sz[k]; i += NTH) {
                float v = src[i];
                s[off + i] = pack2(v, v);
            }
            off += sz[k];
        }
    }
    __syncthreads();

    const float* __restrict__ xin = P.p[0];
    long base = (long)blockIdx.x * (4 * NTH) + threadIdx.x;
    // pair 0 = rows (base, base+NTH); pair 1 = rows (base+2*NTH, base+3*NTH)

    u64 x[2][8];   // running activations, packed 2 rows per lane-pair
    u64 t[2][8];   // scratch

    // ---- load x_in (streaming loads, fully coalesced float4 per row-slice) ----
#pragma unroll
    for (int p = 0; p < 2; p++) {
        long rA = base + (long)(2 * p) * NTH;
        long rB = rA + NTH;
        float4 a0, a1, b0, b1;
        if (rA < N) {
            a0 = __ldcs(reinterpret_cast<const float4*>(xin + rA * 8));
            a1 = __ldcs(reinterpret_cast<const float4*>(xin + rA * 8 + 4));
        } else { a0 = a1 = make_float4(0.f, 0.f, 0.f, 0.f); }
        if (rB < N) {
            b0 = __ldcs(reinterpret_cast<const float4*>(xin + rB * 8));
            b1 = __ldcs(reinterpret_cast<const float4*>(xin + rB * 8 + 4));
        } else { b0 = b1 = make_float4(0.f, 0.f, 0.f, 0.f); }
        x[p][0] = pack2(a0.x, b0.x); x[p][1] = pack2(a0.y, b0.y);
        x[p][2] = pack2(a0.z, b0.z); x[p][3] = pack2(a0.w, b0.w);
        x[p][4] = pack2(a1.x, b1.x); x[p][5] = pack2(a1.y, b1.y);
        x[p][6] = pack2(a1.z, b1.z); x[p][7] = pack2(a1.w, b1.w);
    }

    // ---- encoder ----
    lin<8, 8, true >(s, O_W_IN, O_B_IN, x, t);    // t = rrelu(x @ W_in + b_in)
    lin<8, 4, false>(s, O_W_H1, O_B_H1, t, x);    // x = t @ W_h1 + b_h1

    lin<4, 4, true >(s, O_W_H2, O_B_H2, x, t);    // residual block 1
    lin_add<4, 4>   (s, O_W_H3, O_B_H3, t, x);

    lin<4, 4, true >(s, O_W_H4, O_B_H4, x, t);    // residual block 2
    lin_add<4, 4>   (s, O_W_H5, O_B_H5, t, x);

    lin<4, 1, true >(s, O_W_EN, O_B_EN, x, t);    // t[p][0] = x_encode (2 rows/pair)

    // ---- store x_encode (streaming) ----
#pragma unroll
    for (int p = 0; p < 2; p++) {
        long rA = base + (long)(2 * p) * NTH;
        long rB = rA + NTH;
        float eA, eB;
        unpack2(t[p][0], eA, eB);
        if (rA < N) __stcs(out + rA, eA);
        if (rB < N) __stcs(out + rB, eB);
    }

    // ---- decoder ----
    lin<1, 4, true >(s, O_W_H6, O_B_H6, t, x);    // x = rrelu(e @ W_h6 + b_h6)

    lin<4, 4, true >(s, O_W_H7, O_B_H7, x, t);    // residual block 3
    lin_add<4, 4>   (s, O_W_H8, O_B_H8, t, x);

    lin<4, 4, true >(s, O_W_H9, O_B_H9, x, t);    // residual block 4
    lin_add<4, 4>   (s, O_W_HA, O_B_HA, t, x);

    lin<4, 8, true >(s, O_W_DE, O_B_DE, x, t);    // t = x_decode (8-wide)

    // ---- store x_decode (streaming, two float4 per row) ----
    float* __restrict__ dec = out + N;
#pragma unroll
    for (int p = 0; p < 2; p++) {
        long rA = base + (long)(2 * p) * NTH;
        long rB = rA + NTH;
        float a[8], b[8];
#pragma unroll
        for (int j = 0; j < 8; j++) unpack2(t[p][j], a[j], b[j]);
        if (rA < N) {
            __stcs(reinterpret_cast<float4*>(dec + rA * 8),     make_float4(a[0], a[1], a[2], a[3]));
            __stcs(reinterpret_cast<float4*>(dec + rA * 8 + 4), make_float4(a[4], a[5], a[6], a[7]));
        }
        if (rB < N) {
            __stcs(reinterpret_cast<float4*>(dec + rB * 8),     make_float4(b[0], b[1], b[2], b[3]));
            __stcs(reinterpret_cast<float4*>(dec + rB * 8 + 4), make_float4(b[4], b[5], b[6], b[7]));
        }
    }
}

extern "C" void kernel_launch(void* const* d_in, const int* in_sizes, int n_in,
                              void* d_out, int out_size) {
    Params P;
    for (int k = 0; k < 27; k++) P.p[k] = (const float*)d_in[k];
    int N = in_sizes[0] / 8;                 // 4194304 rows
    int rows_per_block = 4 * NTH;            // 1024
    int blocks = (N + rows_per_block - 1) / rows_per_block;
    ann_fused_kernel<<<blocks, NTH>>>(P, (float*)d_out, N);
}

// round 5
// speedup vs baseline: 1.2398x; 1.2398x over previous
#include <cuda_runtime.h>

#define R    4
#define NTH  256

struct Params { const float* p[27]; };

// Branchless leaky-relu, slope 0.0025: rr(v) = c1*v + c2*|v|,
// c1=(1+s)/2=0.50125, c2=(1-s)/2=0.49875.  v>=0 -> v ; v<0 -> s*v.
// FMUL + FFMA (fabs is a free operand modifier), no predicate.
__device__ __forceinline__ float rr(float v) {
    return fmaf(v, 0.50125f, 0.49875f * fabsf(v));
}

// Shared-memory weight offsets (floats), cumulative over d_in[1..26]:
#define O_W_IN   0
#define O_B_IN   64
#define O_W_H1   72
#define O_B_H1   104
#define O_W_H2   108
#define O_B_H2   124
#define O_W_H3   128
#define O_B_H3   144
#define O_W_H4   148
#define O_B_H4   164
#define O_W_H5   168
#define O_B_H5   184
#define O_W_EN   188
#define O_B_EN   192
#define O_W_H6   193
#define O_B_H6   197
#define O_W_H7   201
#define O_B_H7   217
#define O_W_H8   221
#define O_B_H8   237
#define O_W_H9   241
#define O_B_H9   257
#define O_W_HA   261
#define O_B_HA   277
#define O_W_DE   281
#define O_B_DE   313
#define S_TOTAL  321

// dst[r][j] = (ACT? rr:id)( b[j] + sum_i src[r][i] * W[i*FO+j] )
template<int FI, int FO, bool ACT>
__device__ __forceinline__ void lin(const float* __restrict__ s, int Woff, int boff,
                                    const float (&src)[R][8], float (&dst)[R][8]) {
#pragma unroll
    for (int j = 0; j < FO; j++) {
        float acc[R];
        float bb = s[boff + j];
#pragma unroll
        for (int r = 0; r < R; r++) acc[r] = bb;
#pragma unroll
        for (int i = 0; i < FI; i++) {
            float w = s[Woff + i * FO + j];
#pragma unroll
            for (int r = 0; r < R; r++) acc[r] = fmaf(src[r][i], w, acc[r]);
        }
#pragma unroll
        for (int r = 0; r < R; r++) dst[r][j] = ACT ? rr(acc[r]) : acc[r];
    }
}

// dst[r][j] += b[j] + sum_i src[r][i] * W[i*FO+j]   (residual add)
template<int FI, int FO>
__device__ __forceinline__ void lin_add(const float* __restrict__ s, int Woff, int boff,
                                        const float (&src)[R][8], float (&dst)[R][8]) {
#pragma unroll
    for (int j = 0; j < FO; j++) {
        float acc[R];
        float bb = s[boff + j];
#pragma unroll
        for (int r = 0; r < R; r++) acc[r] = bb;
#pragma unroll
        for (int i = 0; i < FI; i++) {
            float w = s[Woff + i * FO + j];
#pragma unroll
            for (int r = 0; r < R; r++) acc[r] = fmaf(src[r][i], w, acc[r]);
        }
#pragma unroll
        for (int r = 0; r < R; r++) dst[r][j] += acc[r];
    }
}

__global__ __launch_bounds__(NTH, 4)
void ann_fused_kernel(Params P, float* __restrict__ out, int N) {
    __shared__ float s[S_TOTAL];

    // Cooperative weight load: d_in[1..26] -> shared, once per block.
    {
        const int sz[26] = {64,8,32,4,16,4,16,4,16,4,16,4,4,1,4,4,16,4,16,4,16,4,16,4,32,8};
        int off = 0;
        for (int k = 0; k < 26; k++) {
            const float* src = P.p[k + 1];
            for (int i = threadIdx.x; i < sz[k]; i += NTH) s[off + i] = src[i];
            off += sz[k];
        }
    }
    __syncthreads();

    const float* __restrict__ xin = P.p[0];

    // rows fit in 32-bit: N = 4,194,304
    unsigned base = blockIdx.x * (R * NTH) + threadIdx.x;

    float x[R][8];   // running activation (up to 8-wide)
    float t[R][8];   // scratch

    // ---- load x_in rows (two float4 each, streaming, fully coalesced) ----
#pragma unroll
    for (int r = 0; r < R; r++) {
        unsigned row = base + r * NTH;
        if (row < (unsigned)N) {
            float4 a = __ldcs(reinterpret_cast<const float4*>(xin + (size_t)row * 8));
            float4 b = __ldcs(reinterpret_cast<const float4*>(xin + (size_t)row * 8 + 4));
            x[r][0] = a.x; x[r][1] = a.y; x[r][2] = a.z; x[r][3] = a.w;
            x[r][4] = b.x; x[r][5] = b.y; x[r][6] = b.z; x[r][7] = b.w;
        } else {
#pragma unroll
            for (int i = 0; i < 8; i++) x[r][i] = 0.f;
        }
    }

    // ---- encoder ----
    lin<8, 8, true >(s, O_W_IN, O_B_IN, x, t);   // t = rrelu(x @ W_in + b_in)
    lin<8, 4, false>(s, O_W_H1, O_B_H1, t, x);   // x = t @ W_h1 + b_h1

    lin<4, 4, true >(s, O_W_H2, O_B_H2, x, t);   // residual block 1
    lin_add<4, 4>   (s, O_W_H3, O_B_H3, t, x);

    lin<4, 4, true >(s, O_W_H4, O_B_H4, x, t);   // residual block 2
    lin_add<4, 4>   (s, O_W_H5, O_B_H5, t, x);

    lin<4, 1, true >(s, O_W_EN, O_B_EN, x, t);   // t[r][0] = x_encode

    // store x_encode (streaming)
#pragma unroll
    for (int r = 0; r < R; r++) {
        unsigned row = base + r * NTH;
        if (row < (unsigned)N) __stcs(out + row, t[r][0]);
    }

    // ---- decoder ----
    lin<1, 4, true >(s, O_W_H6, O_B_H6, t, x);   // x = rrelu(e @ W_h6 + b_h6)

    lin<4, 4, true >(s, O_W_H7, O_B_H7, x, t);   // residual block 3
    lin_add<4, 4>   (s, O_W_H8, O_B_H8, t, x);

    lin<4, 4, true >(s, O_W_H9, O_B_H9, x, t);   // residual block 4
    lin_add<4, 4>   (s, O_W_HA, O_B_HA, t, x);

    lin<4, 8, true >(s, O_W_DE, O_B_DE, x, t);   // t = x_decode (8-wide)

    // store x_decode (streaming, two float4 per row)
    float* __restrict__ dec = out + N;
#pragma unroll
    for (int r = 0; r < R; r++) {
        unsigned row = base + r * NTH;
        if (row < (unsigned)N) {
            __stcs(reinterpret_cast<float4*>(dec + (size_t)row * 8),
                   make_float4(t[r][0], t[r][1], t[r][2], t[r][3]));
            __stcs(reinterpret_cast<float4*>(dec + (size_t)row * 8 + 4),
                   make_float4(t[r][4], t[r][5], t[r][6], t[r][7]));
        }
    }
}

extern "C" void kernel_launch(void* const* d_in, const int* in_sizes, int n_in,
                              void* d_out, int out_size) {
    Params P;
    for (int k = 0; k < 27; k++) P.p[k] = (const float*)d_in[k];
    int N = in_sizes[0] / 8;                 // 4194304 rows
    int rows_per_block = R * NTH;            // 1024
    int blocks = (N + rows_per_block - 1) / rows_per_block;
    ann_fused_kernel<<<blocks, NTH>>>(P, (float*)d_out, N);
}